// round 8
// baseline (speedup 1.0000x reference)
#include <cuda_runtime.h>
#include <cuda_fp16.h>

#define NUM_SEG 512
#define HALF_SEG 256
#define D4 16          // float4 chunks per row (D=64)
#define CPS 16         // chunks per segment
#define TPB 256
#define CAP 144        // max rows cached in smem per chunk (covers seg len <= 2304)

// Device scratch (reset/overwritten every launch -> deterministic).
__device__ float4 g_psum[NUM_SEG * CPS * D4];
__device__ float  g_psq [NUM_SEG * CPS];
__device__ float4 g_mean[NUM_SEG * D4];
__device__ float  g_inv [NUM_SEG];
__device__ int    g_cnt [NUM_SEG];
__device__ int    g_flag[NUM_SEG];

__device__ __forceinline__ int lower_bound_i32(const int* __restrict__ a, int n, int v) {
    int lo = 0, hi = n;
    while (lo < hi) {
        int mid = (lo + hi) >> 1;
        if (a[mid] < v) lo = mid + 1; else hi = mid;
    }
    return lo;
}

__device__ __forceinline__ uint2 f4_to_h4(float4 v) {
    __half2 lo = __float22half2_rn(make_float2(v.x, v.y));
    __half2 hi = __float22half2_rn(make_float2(v.z, v.w));
    uint2 r;
    r.x = *(unsigned int*)&lo;
    r.y = *(unsigned int*)&hi;
    return r;
}
__device__ __forceinline__ float4 h4_to_f4(uint2 h) {
    float2 a = __half22float2(*(__half2*)&h.x);
    float2 b = __half22float2(*(__half2*)&h.y);
    return make_float4(a.x, a.y, b.x, b.y);
}

__global__ __launch_bounds__(512) void k_init() {
    g_cnt[threadIdx.x]  = 0;
    g_flag[threadIdx.x] = 0;
}

// Phase A for one chunk: stream-read, accumulate, cache fp16, publish partials,
// arrive on segment counter; last arriver finalizes mean + inv.
__device__ __forceinline__ void phaseA_and_arrive(
    const float4* __restrict__ x4,
    int s, int qlo, int nrows, int len,
    int tid, int lane, int wid, int c4, int rg,
    uint2* sh_cache, float4* sh_wsum, float* sh_wsq, float* sh_msq, int* sh_last)
{
    const unsigned FULL = 0xffffffffu;
    const int bid_out = s * CPS + ((tid, 0), 0);  // placeholder removed below
    (void)bid_out;

    float4 sum4 = make_float4(0.f, 0.f, 0.f, 0.f);
    float  sq   = 0.f;
#pragma unroll 2
    for (int rr = rg; rr < nrows; rr += 16) {
        float4 v = __ldcs(&x4[(size_t)(qlo + rr) * D4 + c4]);
        sum4.x += v.x; sum4.y += v.y; sum4.z += v.z; sum4.w += v.w;
        sq += v.x * v.x + v.y * v.y + v.z * v.z + v.w * v.w;
        if (rr < CAP) sh_cache[rr * D4 + c4] = f4_to_h4(v);
    }

    sum4.x += __shfl_down_sync(FULL, sum4.x, 16);
    sum4.y += __shfl_down_sync(FULL, sum4.y, 16);
    sum4.z += __shfl_down_sync(FULL, sum4.z, 16);
    sum4.w += __shfl_down_sync(FULL, sum4.w, 16);
#pragma unroll
    for (int off = 16; off >= 1; off >>= 1)
        sq += __shfl_down_sync(FULL, sq, off);
    if (lane < D4) sh_wsum[wid * D4 + lane] = sum4;
    if (lane == 0) sh_wsq[wid] = sq;
    __syncthreads();

    // chunk index q is encoded by caller through qlo; we need the global slot:
    // caller passes it via sh_last[1]? Keep simple: recompute in caller. Here we
    // receive the slot through sh_last[1] set by caller before call.
    const int slot = sh_last[1];   // s*CPS + q
    if (tid < D4) {
        float4 t = sh_wsum[tid];
#pragma unroll
        for (int w = 1; w < 8; w++) {
            float4 b = sh_wsum[w * D4 + tid];
            t.x += b.x; t.y += b.y; t.z += b.z; t.w += b.w;
        }
        g_psum[slot * D4 + tid] = t;
    }
    if (tid == 0) {
        float t = 0.f;
#pragma unroll
        for (int w = 0; w < 8; w++) t += sh_wsq[w];
        g_psq[slot] = t;
    }
    __threadfence();
    __syncthreads();
    if (tid == 0) sh_last[0] = (atomicAdd(&g_cnt[s], 1) == CPS - 1);
    __syncthreads();

    if (sh_last[0]) {
        const unsigned F2 = 0xffffffffu;
        __threadfence();
        float4 p = __ldcg(&g_psum[s * (CPS * D4) + tid]);  // tid = qq*16 + c4
        p.x += __shfl_down_sync(F2, p.x, 16);
        p.y += __shfl_down_sync(F2, p.y, 16);
        p.z += __shfl_down_sync(F2, p.z, 16);
        p.w += __shfl_down_sync(F2, p.w, 16);
        __syncthreads();               // sh_wsum reuse
        if (lane < D4) sh_wsum[wid * D4 + lane] = p;
        __syncthreads();
        const float invc = 1.f / (float)max(len, 1);
        if (tid < D4) {
            float4 t = sh_wsum[tid];
#pragma unroll
            for (int w = 1; w < 8; w++) {
                float4 b = sh_wsum[w * D4 + tid];
                t.x += b.x; t.y += b.y; t.z += b.z; t.w += b.w;
            }
            float4 m = make_float4(t.x * invc, t.y * invc, t.z * invc, t.w * invc);
            g_mean[s * D4 + tid] = m;
            sh_msq[tid] = m.x * m.x + m.y * m.y + m.z * m.z + m.w * m.w;
        }
        __syncthreads();
        if (tid == 0) {
            float sq_tot = 0.f, msq = 0.f;
#pragma unroll
            for (int i = 0; i < CPS; i++) sq_tot += __ldcg(&g_psq[s * CPS + i]);
#pragma unroll
            for (int i = 0; i < D4; i++) msq += sh_msq[i];
            float var = sq_tot * invc - msq;   // E|x|^2 - |m|^2
            g_inv[s] = rsqrtf(var);
            __threadfence();
            atomicExch(&g_flag[s], 1);
        }
        __syncthreads();
    }
}

__device__ __forceinline__ void wait_and_phaseB(
    const float4* __restrict__ x4, float4* __restrict__ out4,
    int s, int qlo, int nrows,
    int tid, int c4, int rg, const uint2* sh_cache)
{
    if (tid == 0) {
        while (((volatile int*)g_flag)[s] == 0) __nanosleep(128);
    }
    __syncthreads();
    __threadfence();

    const float4 m  = __ldcg(&g_mean[s * D4 + c4]);
    const float  gi = __ldcg(&g_inv[s]);
#pragma unroll 2
    for (int rr = rg; rr < nrows; rr += 16) {
        const size_t idx = (size_t)(qlo + rr) * D4 + c4;
        float4 v;
        if (rr < CAP) v = h4_to_f4(sh_cache[rr * D4 + c4]);
        else          v = __ldcg(&x4[idx]);   // rare overflow fallback
        float4 o;
        o.x = (v.x - m.x) * gi;
        o.y = (v.y - m.y) * gi;
        o.z = (v.z - m.z) * gi;
        o.w = (v.w - m.w) * gi;
        __stcs(&out4[idx], o);
    }
}

__global__ __launch_bounds__(TPB) void k_fused(
    const float4* __restrict__ x4,   // [N,16]
    const int* __restrict__ batch,   // [N] sorted int32
    float4* __restrict__ out4,
    int N)
{
    const int bid = blockIdx.x;      // 0 .. 4095
    const int s0  = bid >> 4;        // 0..255
    const int q   = bid & 15;
    const int s1  = s0 + HALF_SEG;   // 256..511
    const int tid = threadIdx.x;
    const int lane = tid & 31;
    const int wid  = tid >> 5;
    const int c4 = tid & (D4 - 1);
    const int rg = tid >> 4;

    __shared__ uint2  sh_x0[CAP * D4];   // 18.4 KB
    __shared__ uint2  sh_x1[CAP * D4];   // 18.4 KB
    __shared__ float4 sh_wsum[8 * D4];
    __shared__ float  sh_wsq[8];
    __shared__ float  sh_msq[D4];
    __shared__ int    sh_last[2];        // [0]=last flag, [1]=slot id
    __shared__ int    sh_b[4];           // lo0, hi0, lo1, hi1

    if (tid == 0)  sh_b[0] = lower_bound_i32(batch, N, s0);
    if (tid == 32) sh_b[1] = lower_bound_i32(batch, N, s0 + 1);
    if (tid == 64) sh_b[2] = lower_bound_i32(batch, N, s1);
    if (tid == 96) sh_b[3] = lower_bound_i32(batch, N, s1 + 1);
    __syncthreads();
    const int lo0 = sh_b[0], len0 = sh_b[1] - sh_b[0];
    const int lo1 = sh_b[2], len1 = sh_b[3] - sh_b[2];
    const int qlo0 = lo0 + ((len0 * q) >> 4);
    const int qhi0 = lo0 + ((len0 * (q + 1)) >> 4);
    const int qlo1 = lo1 + ((len1 * q) >> 4);
    const int qhi1 = lo1 + ((len1 * (q + 1)) >> 4);

    // ---- A(s0) ----
    if (tid == 0) sh_last[1] = s0 * CPS + q;
    __syncthreads();
    phaseA_and_arrive(x4, s0, qlo0, qhi0 - qlo0, len0,
                      tid, lane, wid, c4, rg,
                      sh_x0, sh_wsum, sh_wsq, sh_msq, sh_last);
    __syncthreads();

    // ---- A(s1) (fills the wait bubble of s0) ----
    if (tid == 0) sh_last[1] = s1 * CPS + q;
    __syncthreads();
    phaseA_and_arrive(x4, s1, qlo1, qhi1 - qlo1, len1,
                      tid, lane, wid, c4, rg,
                      sh_x1, sh_wsum, sh_wsq, sh_msq, sh_last);
    __syncthreads();

    // ---- B(s0) then B(s1) ----
    wait_and_phaseB(x4, out4, s0, qlo0, qhi0 - qlo0, tid, c4, rg, sh_x0);
    wait_and_phaseB(x4, out4, s1, qlo1, qhi1 - qlo1, tid, c4, rg, sh_x1);
}

extern "C" void kernel_launch(void* const* d_in, const int* in_sizes, int n_in,
                              void* d_out, int out_size)
{
    const float* x     = (const float*)d_in[0];   // [N, 64]
    const int*   batch = (const int*)d_in[1];     // [N], sorted int32
    float*       out   = (float*)d_out;
    const int N = in_sizes[1];

    k_init<<<1, NUM_SEG>>>();
    k_fused<<<HALF_SEG * CPS, TPB>>>((const float4*)x, batch, (float4*)out, N);
}

// round 10
// speedup vs baseline: 1.0935x; 1.0935x over previous
#include <cuda_runtime.h>
#include <cuda_fp16.h>

#define NUM_SEG 512
#define D4 16          // float4 chunks per row (D=64)
#define CPS 8          // chunks per segment
#define TPB 512
#define NWARP (TPB / 32)
#define RGN 32         // row groups (TPB / D4)
#define CAP 288        // max rows cached in smem per chunk (covers seg len <= 2304)

// Device scratch (reset/overwritten every launch -> deterministic).
__device__ float4 g_psum[NUM_SEG * CPS * D4];
__device__ float  g_psq [NUM_SEG * CPS];
__device__ int    g_cnt [NUM_SEG];

__device__ __forceinline__ int lower_bound_i32(const int* __restrict__ a, int n, int v) {
    int lo = 0, hi = n;
    while (lo < hi) {
        int mid = (lo + hi) >> 1;
        if (a[mid] < v) lo = mid + 1; else hi = mid;
    }
    return lo;
}

__device__ __forceinline__ uint2 f4_to_h4(float4 v) {
    __half2 lo = __float22half2_rn(make_float2(v.x, v.y));
    __half2 hi = __float22half2_rn(make_float2(v.z, v.w));
    uint2 r;
    r.x = *(unsigned int*)&lo;
    r.y = *(unsigned int*)&hi;
    return r;
}
__device__ __forceinline__ float4 h4_to_f4(uint2 h) {
    float2 a = __half22float2(*(__half2*)&h.x);
    float2 b = __half22float2(*(__half2*)&h.y);
    return make_float4(a.x, a.y, b.x, b.y);
}

__global__ __launch_bounds__(NUM_SEG) void k_init() {
    g_cnt[threadIdx.x] = 0;
}

__global__ __launch_bounds__(TPB) void k_fused(
    const float4* __restrict__ x4,   // [N,16]
    const int* __restrict__ batch,   // [N] sorted int32
    float4* __restrict__ out4,
    int N)
{
    const int bid = blockIdx.x;      // 0 .. 4095
    const int s   = bid >> 3;        // segment 0..511
    const int q   = bid & 7;         // chunk 0..7
    const int tid = threadIdx.x;
    const int lane = tid & 31;
    const int wid  = tid >> 5;       // 0..15
    const int c4 = tid & (D4 - 1);   // column chunk 0..15
    const int rg = tid >> 4;         // row group 0..31

    __shared__ uint2  sh_x[CAP * D4];          // 36.9 KB fp16 chunk cache
    __shared__ float4 sh_wsum[NWARP * D4];     // 4 KB
    __shared__ float  sh_wsq[NWARP];
    __shared__ float4 sh_fin[CPS * D4];        // 2 KB (finalize staging)
    __shared__ float4 sh_mean[D4];
    __shared__ float  sh_msq[D4];
    __shared__ float  sh_inv;
    __shared__ int    sh_b[2];

    if (tid == 0)  sh_b[0] = lower_bound_i32(batch, N, s);
    if (tid == 32) sh_b[1] = lower_bound_i32(batch, N, s + 1);
    __syncthreads();
    const int lo = sh_b[0], len = sh_b[1] - sh_b[0];
    const int qlo = lo + ((len * q) >> 3);
    const int qhi = lo + ((len * (q + 1)) >> 3);
    const int nrows = qhi - qlo;

    // ---- Phase A: stream-read chunk, accumulate, cache fp16 in smem ----
    const unsigned FULL = 0xffffffffu;
    float4 sum4 = make_float4(0.f, 0.f, 0.f, 0.f);
    float  sq   = 0.f;
#pragma unroll 2
    for (int rr = rg; rr < nrows; rr += RGN) {
        float4 v = __ldcs(&x4[(size_t)(qlo + rr) * D4 + c4]);
        sum4.x += v.x; sum4.y += v.y; sum4.z += v.z; sum4.w += v.w;
        sq += v.x * v.x + v.y * v.y + v.z * v.z + v.w * v.w;
        if (rr < CAP) sh_x[rr * D4 + c4] = f4_to_h4(v);
    }

    // warp reduce: lane+16 shares c4
    sum4.x += __shfl_down_sync(FULL, sum4.x, 16);
    sum4.y += __shfl_down_sync(FULL, sum4.y, 16);
    sum4.z += __shfl_down_sync(FULL, sum4.z, 16);
    sum4.w += __shfl_down_sync(FULL, sum4.w, 16);
#pragma unroll
    for (int off = 16; off >= 1; off >>= 1)
        sq += __shfl_down_sync(FULL, sq, off);
    if (lane < D4) sh_wsum[wid * D4 + lane] = sum4;
    if (lane == 0) sh_wsq[wid] = sq;
    __syncthreads();

    if (tid < D4) {
        float4 t = sh_wsum[tid];
#pragma unroll
        for (int w = 1; w < NWARP; w++) {
            float4 b = sh_wsum[w * D4 + tid];
            t.x += b.x; t.y += b.y; t.z += b.z; t.w += b.w;
        }
        g_psum[bid * D4 + tid] = t;
    }
    if (tid == 32) {
        float t = 0.f;
#pragma unroll
        for (int w = 0; w < NWARP; w++) t += sh_wsq[w];
        g_psq[bid] = t;
    }
    __threadfence();
    __syncthreads();
    if (tid == 0) {
        atomicAdd(&g_cnt[s], 1);
        // spin until all CPS siblings have published
        while (((volatile int*)g_cnt)[s] < CPS) __nanosleep(64);
    }
    __syncthreads();
    __threadfence();

    // ---- Redundant decentralized finalize (every block, in smem) ----
    if (tid < CPS * D4) {           // 128 threads: qq = tid>>4, c4 = tid&15
        sh_fin[tid] = __ldcg(&g_psum[s * (CPS * D4) + tid]);
    }
    __syncthreads();
    const float invc = 1.f / (float)max(len, 1);
    if (tid < D4) {
        float4 t = sh_fin[tid];
#pragma unroll
        for (int qq = 1; qq < CPS; qq++) {
            float4 b = sh_fin[qq * D4 + tid];
            t.x += b.x; t.y += b.y; t.z += b.z; t.w += b.w;
        }
        float4 m = make_float4(t.x * invc, t.y * invc, t.z * invc, t.w * invc);
        sh_mean[tid] = m;
        sh_msq[tid] = m.x * m.x + m.y * m.y + m.z * m.z + m.w * m.w;
    }
    __syncthreads();
    if (tid == 0) {
        float sq_tot = 0.f, msq = 0.f;
#pragma unroll
        for (int i = 0; i < CPS; i++) sq_tot += __ldcg(&g_psq[s * CPS + i]);
#pragma unroll
        for (int i = 0; i < D4; i++) msq += sh_msq[i];
        // segment_mean(|x-m|^2) = segment_mean(|x|^2) - |m|^2
        float var = sq_tot * invc - msq;
        sh_inv = rsqrtf(var);
    }
    __syncthreads();

    // ---- Phase B: apply from smem fp16 cache, streaming fp32 output ----
    const float4 m  = sh_mean[c4];
    const float  gi = sh_inv;
#pragma unroll 2
    for (int rr = rg; rr < nrows; rr += RGN) {
        const size_t idx = (size_t)(qlo + rr) * D4 + c4;
        float4 v;
        if (rr < CAP) v = h4_to_f4(sh_x[rr * D4 + c4]);
        else          v = __ldcg(&x4[idx]);   // rare overflow fallback
        float4 o;
        o.x = (v.x - m.x) * gi;
        o.y = (v.y - m.y) * gi;
        o.z = (v.z - m.z) * gi;
        o.w = (v.w - m.w) * gi;
        __stcs(&out4[idx], o);
    }
}

extern "C" void kernel_launch(void* const* d_in, const int* in_sizes, int n_in,
                              void* d_out, int out_size)
{
    const float* x     = (const float*)d_in[0];   // [N, 64]
    const int*   batch = (const int*)d_in[1];     // [N], sorted int32
    float*       out   = (float*)d_out;
    const int N = in_sizes[1];

    k_init<<<1, NUM_SEG>>>();
    k_fused<<<NUM_SEG * CPS, TPB>>>((const float4*)x, batch, (float4*)out, N);
}